// round 9
// baseline (speedup 1.0000x reference)
#include <cuda_runtime.h>
#include <cuda_fp16.h>
#include <cstdint>
#include <cstddef>

// ----------------------------------------------------------------------------
// Problem constants
// ----------------------------------------------------------------------------
#define MDIM 8192   // B*S = 4*2048
#define NDIM 4096   // OUT_DIM
#define KDIM 4096   // IN_DIM

// GEMM tiling
#define BM 128
#define BN 256
#define BK 64                       // fp16 elems per K chunk = 128 B rows
#define NKITER (KDIM / BK)          // 64
#define STAGES 4
#define A_STG 16384                 // 128 rows * 128 B
#define B_STG 32768                 // 256 rows * 128 B
#define STG (A_STG + B_STG)         // 49152
#define GEMM_SMEM (STAGES * STG)    // 196608

// Pre-tiled, pre-swizzled staging buffers (prep kernels write; GEMM cp.asyncs)
__device__ __align__(1024) __half g_x16[(size_t)MDIM * KDIM];  // 64 MB
__device__ __align__(1024) __half g_w16[(size_t)NDIM * KDIM];  // 32 MB

__constant__ float c_nf4[16] = {
    -1.0f, -0.6961928009986877f, -0.5250730514526367f, -0.39491748809814453f,
    -0.28444138169288635f, -0.18477343022823334f, -0.09105003625154495f, 0.0f,
    0.07958029955625534f, 0.16093020141124725f, 0.24611230194568634f,
    0.33791524171829224f, 0.44070982933044434f, 0.5626170039176941f,
    0.7229568362236328f, 1.0f};

// ----------------------------------------------------------------------------
// Helpers
// ----------------------------------------------------------------------------
__device__ __forceinline__ uint32_t smem_u32(const void* p) {
    uint32_t a;
    asm("{ .reg .u64 t; cvta.to.shared.u64 t, %1; cvt.u32.u64 %0, t; }" : "=r"(a) : "l"(p));
    return a;
}
__device__ __forceinline__ uint32_t swz128(uint32_t o) { return o ^ ((o >> 3) & 0x70); }
__device__ __forceinline__ uint32_t h2u(__half2 h) { return *reinterpret_cast<uint32_t*>(&h); }

__device__ __forceinline__ void cp16(uint32_t dst, const void* src) {
    asm volatile("cp.async.cg.shared.global [%0], [%1], 16;" :: "r"(dst), "l"(src));
}
__device__ __forceinline__ void cp_commit() {
    asm volatile("cp.async.commit_group;" ::: "memory");
}
template <int N>
__device__ __forceinline__ void cp_wait() {
    asm volatile("cp.async.wait_group %0;" :: "n"(N) : "memory");
}
__device__ __forceinline__ void ldm_x4(uint32_t* r, uint32_t addr) {
    asm volatile("ldmatrix.sync.aligned.m8n8.x4.shared.b16 {%0,%1,%2,%3}, [%4];"
                 : "=r"(r[0]), "=r"(r[1]), "=r"(r[2]), "=r"(r[3]) : "r"(addr));
}
__device__ __forceinline__ void mma16816(float* c, const uint32_t* a, uint32_t b0, uint32_t b1) {
    asm volatile(
        "mma.sync.aligned.m16n8k16.row.col.f32.f16.f16.f32 "
        "{%0,%1,%2,%3}, {%4,%5,%6,%7}, {%8,%9}, {%0,%1,%2,%3};"
        : "+f"(c[0]), "+f"(c[1]), "+f"(c[2]), "+f"(c[3])
        : "r"(a[0]), "r"(a[1]), "r"(a[2]), "r"(a[3]), "r"(b0), "r"(b1));
}

// ----------------------------------------------------------------------------
// Kernel 1: x fp32 -> fp16 in (m_tile, k_chunk)-blocked SW128 layout.
// Block (mt,kc) is 16 KB at byte offset ((mt*64+kc)<<14); element (r,c) inside
// at swz128(r*128 + c*2) = r*128 + ((c*2) ^ ((r&7)<<4)).
// ----------------------------------------------------------------------------
__global__ void __launch_bounds__(256) convert_x_kernel(const float* __restrict__ x) {
    size_t t = (size_t)blockIdx.x * blockDim.x + threadIdx.x;
    size_t base = t * 8;
    const float4* xp = reinterpret_cast<const float4*>(x + base);
    float4 f0 = __ldg(xp), f1 = __ldg(xp + 1);
    uint32_t m = (uint32_t)(base >> 12);
    uint32_t k = (uint32_t)(base & 4095);
    uint32_t mt = m >> 7, r = m & 127, kc = k >> 6, c = k & 63;
    uint32_t off = swz128((r << 7) | (c << 1));
    uint4 v;
    v.x = h2u(__floats2half2_rn(f0.x, f0.y));
    v.y = h2u(__floats2half2_rn(f0.z, f0.w));
    v.z = h2u(__floats2half2_rn(f1.x, f1.y));
    v.w = h2u(__floats2half2_rn(f1.z, f1.w));
    *reinterpret_cast<uint4*>(reinterpret_cast<char*>(g_x16) +
                              (((size_t)(mt * 64 + kc)) << 14) + off) = v;
}

// ----------------------------------------------------------------------------
// Kernel 2: W_eff = nf4[codes]*scale + 2.0*(b@a), fp16, (n_tile=256-row,
// k_chunk)-blocked SW128 layout. One block = 16 output rows x full K.
// ----------------------------------------------------------------------------
__global__ void __launch_bounds__(256) dequant_kernel(
    const int* __restrict__ codes, const float* __restrict__ scales,
    const float* __restrict__ la, const float* __restrict__ lb) {
    __shared__ float a_sm[16 * 512];     // lora_a chunk [16][512]
    __shared__ float s_scale[16 * 64];
    __shared__ float s_b[16 * 16];
    __shared__ float s_nf4[16];
    const int tid = threadIdx.x;
    const int ob = blockIdx.x * 16;

    for (int i = tid; i < 1024; i += 256) s_scale[i] = scales[(size_t)ob * 64 + i];
    s_b[tid] = lb[(size_t)ob * 16 + tid] * 2.0f;  // fold alpha/rank = 2
    if (tid < 16) s_nf4[tid] = c_nf4[tid];

    const int q = tid >> 6;       // row quad 0..3
    const int oct = tid & 63;     // col octet within 512-col chunk
    const float4* lap = reinterpret_cast<const float4*>(la);
    float4* a4 = reinterpret_cast<float4*>(a_sm);

    for (int c8 = 0; c8 < 8; c8++) {
        __syncthreads();
        for (int i = tid; i < 2048; i += 256) {
            int r = i >> 7, j = i & 127;
            a4[i] = __ldg(lap + (size_t)r * 1024 + c8 * 128 + j);
        }
        __syncthreads();

        const int i0 = c8 * 512 + oct * 8;  // absolute column
        float acc[4][8];
        #pragma unroll
        for (int rr = 0; rr < 4; rr++) {
            const int o = ob + q * 4 + rr;
            const int4* cp = reinterpret_cast<const int4*>(codes + (size_t)o * 4096 + i0);
            int4 c0 = __ldg(cp), c1 = __ldg(cp + 1);
            float sc = s_scale[(q * 4 + rr) * 64 + (i0 >> 6)];
            acc[rr][0] = s_nf4[c0.x & 15] * sc;
            acc[rr][1] = s_nf4[c0.y & 15] * sc;
            acc[rr][2] = s_nf4[c0.z & 15] * sc;
            acc[rr][3] = s_nf4[c0.w & 15] * sc;
            acc[rr][4] = s_nf4[c1.x & 15] * sc;
            acc[rr][5] = s_nf4[c1.y & 15] * sc;
            acc[rr][6] = s_nf4[c1.z & 15] * sc;
            acc[rr][7] = s_nf4[c1.w & 15] * sc;
        }
        #pragma unroll
        for (int r = 0; r < 16; r++) {
            float4 a0 = a4[r * 128 + oct * 2];
            float4 a1 = a4[r * 128 + oct * 2 + 1];
            #pragma unroll
            for (int rr = 0; rr < 4; rr++) {
                float bv = s_b[(q * 4 + rr) * 16 + r];
                acc[rr][0] += bv * a0.x; acc[rr][1] += bv * a0.y;
                acc[rr][2] += bv * a0.z; acc[rr][3] += bv * a0.w;
                acc[rr][4] += bv * a1.x; acc[rr][5] += bv * a1.y;
                acc[rr][6] += bv * a1.z; acc[rr][7] += bv * a1.w;
            }
        }
        #pragma unroll
        for (int rr = 0; rr < 4; rr++) {
            const int o = ob + q * 4 + rr;
            uint4 v;
            v.x = h2u(__floats2half2_rn(acc[rr][0], acc[rr][1]));
            v.y = h2u(__floats2half2_rn(acc[rr][2], acc[rr][3]));
            v.z = h2u(__floats2half2_rn(acc[rr][4], acc[rr][5]));
            v.w = h2u(__floats2half2_rn(acc[rr][6], acc[rr][7]));
            size_t blk = ((size_t)((o >> 8) * 64 + (i0 >> 6))) << 15;
            uint32_t inner = swz128(((o & 255) << 7) | ((i0 & 63) << 1));
            *reinterpret_cast<uint4*>(reinterpret_cast<char*>(g_w16) + blk + inner) = v;
        }
    }
}

// ----------------------------------------------------------------------------
// Kernel 3: HMMA GEMM, CTA 128x256, BK=64, 4-stage cp.async pipeline.
// 512 threads = 16 warps (4m x 4n, 32x64 warp tiles) -> 4 warps/SMSP for
// TLP-based latency hiding; fragments single-buffered (reg budget 128).
// ----------------------------------------------------------------------------
__global__ void __launch_bounds__(512, 1) gemm_kernel(float* __restrict__ out) {
    extern __shared__ char smem[];
    const uint32_t sb = smem_u32(smem);
    const int tid = threadIdx.x;
    const int lane = tid & 31, wid = tid >> 5;
    const int wm = wid >> 2, wn = wid & 3;      // warp tile: 32x64
    const int bid = blockIdx.x;
    const int nt = bid & 15, mt = bid >> 4;     // n-minor: W stays L2-resident

    const char* ablock = reinterpret_cast<const char*>(g_x16) + (((size_t)mt * 64) << 14);
    const char* bblock = reinterpret_cast<const char*>(g_w16) + (((size_t)nt * 64) << 15);

    // stage fill: contiguous memcpy (layout is pre-swizzled); 6 cp16/thread
    auto load_stage = [&](int chunk, int slot) {
        uint32_t sA = sb + slot * STG;
        const char* as = ablock + ((size_t)chunk << 14);
        #pragma unroll
        for (int p = 0; p < 2; p++)
            cp16(sA + tid * 16 + p * 8192, as + tid * 16 + p * 8192);
        uint32_t sB = sA + A_STG;
        const char* bs = bblock + ((size_t)chunk << 15);
        #pragma unroll
        for (int p = 0; p < 4; p++)
            cp16(sB + tid * 16 + p * 8192, bs + tid * 16 + p * 8192);
    };

    #pragma unroll
    for (int s = 0; s < STAGES - 1; s++) { load_stage(s, s); cp_commit(); }

    // per-lane ldmatrix address components
    const uint32_t xorv   = (lane & 7) << 4;
    const uint32_t arow_l = ((lane >> 3) & 1) * 8 + (lane & 7);
    const uint32_t acol_l = (lane >> 4) * 16;            // byte col half
    const uint32_t nrow_l = ((lane >> 4) << 3) + (lane & 7);
    const uint32_t bcol_l = ((lane >> 3) & 1) * 16;      // byte col half

    float acc[2][8][4];
    #pragma unroll
    for (int i = 0; i < 2; i++)
        #pragma unroll
        for (int j = 0; j < 8; j++)
            #pragma unroll
            for (int c = 0; c < 4; c++) acc[i][j][c] = 0.f;

    for (int i = 0; i < NKITER; i++) {
        cp_wait<STAGES - 2>();
        __syncthreads();
        int nexti = i + STAGES - 1;
        if (nexti < NKITER) load_stage(nexti, nexti & (STAGES - 1));
        cp_commit();

        const uint32_t aS = sb + (i & (STAGES - 1)) * STG;
        const uint32_t bS = aS + A_STG;
        #pragma unroll
        for (int ks = 0; ks < 4; ks++) {
            uint32_t a[2][4];
            #pragma unroll
            for (int mf = 0; mf < 2; mf++) {
                uint32_t arow = wm * 32 + mf * 16 + arow_l;
                ldm_x4(a[mf], aS + arow * 128 + (((uint32_t)(ks * 32) + acol_l) ^ xorv));
            }
            #pragma unroll
            for (int np = 0; np < 4; np++) {
                uint32_t b[4];
                uint32_t nrow = wn * 64 + np * 16 + nrow_l;
                ldm_x4(b, bS + nrow * 128 + (((uint32_t)(ks * 32) + bcol_l) ^ xorv));
                #pragma unroll
                for (int mf = 0; mf < 2; mf++) {
                    mma16816(acc[mf][2 * np],     a[mf], b[0], b[1]);
                    mma16816(acc[mf][2 * np + 1], a[mf], b[2], b[3]);
                }
            }
        }
    }

    // epilogue: direct fp32 stores
    #pragma unroll
    for (int mf = 0; mf < 2; mf++) {
        size_t row0 = (size_t)mt * BM + wm * 32 + mf * 16 + (lane >> 2);
        float* r0 = out + row0 * NDIM + (size_t)nt * BN + wn * 64 + (lane & 3) * 2;
        float* r1 = r0 + 8 * NDIM;
        #pragma unroll
        for (int nf = 0; nf < 8; nf++) {
            *reinterpret_cast<float2*>(r0 + nf * 8) = make_float2(acc[mf][nf][0], acc[mf][nf][1]);
            *reinterpret_cast<float2*>(r1 + nf * 8) = make_float2(acc[mf][nf][2], acc[mf][nf][3]);
        }
    }
}

// ----------------------------------------------------------------------------
// Launch
// ----------------------------------------------------------------------------
extern "C" void kernel_launch(void* const* d_in, const int* in_sizes, int n_in,
                              void* d_out, int out_size) {
    const float* x      = (const float*)d_in[0];
    const int*   codes  = (const int*)d_in[1];
    const float* scales = (const float*)d_in[2];
    const float* la     = (const float*)d_in[3];
    const float* lb     = (const float*)d_in[4];
    float* out = (float*)d_out;
    (void)in_sizes; (void)n_in; (void)out_size;

    cudaFuncSetAttribute(gemm_kernel, cudaFuncAttributeMaxDynamicSharedMemorySize, GEMM_SMEM);

    convert_x_kernel<<<(MDIM * (size_t)KDIM) / 8 / 256, 256>>>(x);
    dequant_kernel<<<NDIM / 16, 256>>>(codes, scales, la, lb);
    gemm_kernel<<<(MDIM / BM) * (NDIM / BN), 512, GEMM_SMEM>>>(out);
}

// round 10
// speedup vs baseline: 1.0447x; 1.0447x over previous
#include <cuda_runtime.h>
#include <cuda_fp16.h>
#include <cstdint>
#include <cstddef>

// ----------------------------------------------------------------------------
// Problem constants
// ----------------------------------------------------------------------------
#define MDIM 8192   // B*S = 4*2048
#define NDIM 4096   // OUT_DIM
#define KDIM 4096   // IN_DIM

// GEMM tiling: CTA 128x128, 128 threads, 2 CTAs/SM, 3-stage pipeline
#define BM 128
#define BN 128
#define BK 64                       // fp16 elems per K chunk = 128 B rows
#define NKITER (KDIM / BK)          // 64
#define STAGES 3
#define A_STG 16384                 // 128 rows * 128 B
#define B_STG 16384                 // 128 rows * 128 B
#define STG (A_STG + B_STG)         // 32768
#define GEMM_SMEM (STAGES * STG)    // 98304 -> 2 CTAs/SM (196608 <= 227KB)

// Pre-tiled, pre-swizzled staging buffers (prep kernels write; GEMM cp.asyncs)
__device__ __align__(1024) __half g_x16[(size_t)MDIM * KDIM];  // 64 MB
__device__ __align__(1024) __half g_w16[(size_t)NDIM * KDIM];  // 32 MB

__constant__ float c_nf4[16] = {
    -1.0f, -0.6961928009986877f, -0.5250730514526367f, -0.39491748809814453f,
    -0.28444138169288635f, -0.18477343022823334f, -0.09105003625154495f, 0.0f,
    0.07958029955625534f, 0.16093020141124725f, 0.24611230194568634f,
    0.33791524171829224f, 0.44070982933044434f, 0.5626170039176941f,
    0.7229568362236328f, 1.0f};

// ----------------------------------------------------------------------------
// Helpers
// ----------------------------------------------------------------------------
__device__ __forceinline__ uint32_t smem_u32(const void* p) {
    uint32_t a;
    asm("{ .reg .u64 t; cvta.to.shared.u64 t, %1; cvt.u32.u64 %0, t; }" : "=r"(a) : "l"(p));
    return a;
}
__device__ __forceinline__ uint32_t swz128(uint32_t o) { return o ^ ((o >> 3) & 0x70); }
__device__ __forceinline__ uint32_t h2u(__half2 h) { return *reinterpret_cast<uint32_t*>(&h); }

__device__ __forceinline__ void cp16(uint32_t dst, const void* src) {
    asm volatile("cp.async.cg.shared.global [%0], [%1], 16;" :: "r"(dst), "l"(src));
}
__device__ __forceinline__ void cp_commit() {
    asm volatile("cp.async.commit_group;" ::: "memory");
}
template <int N>
__device__ __forceinline__ void cp_wait() {
    asm volatile("cp.async.wait_group %0;" :: "n"(N) : "memory");
}
__device__ __forceinline__ void ldm_x4(uint32_t* r, uint32_t addr) {
    asm volatile("ldmatrix.sync.aligned.m8n8.x4.shared.b16 {%0,%1,%2,%3}, [%4];"
                 : "=r"(r[0]), "=r"(r[1]), "=r"(r[2]), "=r"(r[3]) : "r"(addr));
}
__device__ __forceinline__ void mma16816(float* c, const uint32_t* a, uint32_t b0, uint32_t b1) {
    asm volatile(
        "mma.sync.aligned.m16n8k16.row.col.f32.f16.f16.f32 "
        "{%0,%1,%2,%3}, {%4,%5,%6,%7}, {%8,%9}, {%0,%1,%2,%3};"
        : "+f"(c[0]), "+f"(c[1]), "+f"(c[2]), "+f"(c[3])
        : "r"(a[0]), "r"(a[1]), "r"(a[2]), "r"(a[3]), "r"(b0), "r"(b1));
}

// ----------------------------------------------------------------------------
// Kernel 1: x fp32 -> fp16 in (m_tile, k_chunk)-blocked SW128 layout.
// Block (mt,kc) is 16 KB at byte offset ((mt*64+kc)<<14); element (r,c) inside
// at swz128(r*128 + c*2) = r*128 + ((c*2) ^ ((r&7)<<4)).
// ----------------------------------------------------------------------------
__global__ void __launch_bounds__(256) convert_x_kernel(const float* __restrict__ x) {
    size_t t = (size_t)blockIdx.x * blockDim.x + threadIdx.x;
    size_t base = t * 8;
    const float4* xp = reinterpret_cast<const float4*>(x + base);
    float4 f0 = __ldg(xp), f1 = __ldg(xp + 1);
    uint32_t m = (uint32_t)(base >> 12);
    uint32_t k = (uint32_t)(base & 4095);
    uint32_t mt = m >> 7, r = m & 127, kc = k >> 6, c = k & 63;
    uint32_t off = swz128((r << 7) | (c << 1));
    uint4 v;
    v.x = h2u(__floats2half2_rn(f0.x, f0.y));
    v.y = h2u(__floats2half2_rn(f0.z, f0.w));
    v.z = h2u(__floats2half2_rn(f1.x, f1.y));
    v.w = h2u(__floats2half2_rn(f1.z, f1.w));
    *reinterpret_cast<uint4*>(reinterpret_cast<char*>(g_x16) +
                              (((size_t)(mt * 64 + kc)) << 14) + off) = v;
}

// ----------------------------------------------------------------------------
// Kernel 2: W_eff = nf4[codes]*scale + 2.0*(b@a), fp16, (n_tile=256-row,
// k_chunk)-blocked SW128 layout. One block = 16 output rows x full K.
// ----------------------------------------------------------------------------
__global__ void __launch_bounds__(256) dequant_kernel(
    const int* __restrict__ codes, const float* __restrict__ scales,
    const float* __restrict__ la, const float* __restrict__ lb) {
    __shared__ float a_sm[16 * 512];     // lora_a chunk [16][512]
    __shared__ float s_scale[16 * 64];
    __shared__ float s_b[16 * 16];
    __shared__ float s_nf4[16];
    const int tid = threadIdx.x;
    const int ob = blockIdx.x * 16;

    for (int i = tid; i < 1024; i += 256) s_scale[i] = scales[(size_t)ob * 64 + i];
    s_b[tid] = lb[(size_t)ob * 16 + tid] * 2.0f;  // fold alpha/rank = 2
    if (tid < 16) s_nf4[tid] = c_nf4[tid];

    const int q = tid >> 6;       // row quad 0..3
    const int oct = tid & 63;     // col octet within 512-col chunk
    const float4* lap = reinterpret_cast<const float4*>(la);
    float4* a4 = reinterpret_cast<float4*>(a_sm);

    for (int c8 = 0; c8 < 8; c8++) {
        __syncthreads();
        for (int i = tid; i < 2048; i += 256) {
            int r = i >> 7, j = i & 127;
            a4[i] = __ldg(lap + (size_t)r * 1024 + c8 * 128 + j);
        }
        __syncthreads();

        const int i0 = c8 * 512 + oct * 8;  // absolute column
        float acc[4][8];
        #pragma unroll
        for (int rr = 0; rr < 4; rr++) {
            const int o = ob + q * 4 + rr;
            const int4* cp = reinterpret_cast<const int4*>(codes + (size_t)o * 4096 + i0);
            int4 c0 = __ldg(cp), c1 = __ldg(cp + 1);
            float sc = s_scale[(q * 4 + rr) * 64 + (i0 >> 6)];
            acc[rr][0] = s_nf4[c0.x & 15] * sc;
            acc[rr][1] = s_nf4[c0.y & 15] * sc;
            acc[rr][2] = s_nf4[c0.z & 15] * sc;
            acc[rr][3] = s_nf4[c0.w & 15] * sc;
            acc[rr][4] = s_nf4[c1.x & 15] * sc;
            acc[rr][5] = s_nf4[c1.y & 15] * sc;
            acc[rr][6] = s_nf4[c1.z & 15] * sc;
            acc[rr][7] = s_nf4[c1.w & 15] * sc;
        }
        #pragma unroll
        for (int r = 0; r < 16; r++) {
            float4 a0 = a4[r * 128 + oct * 2];
            float4 a1 = a4[r * 128 + oct * 2 + 1];
            #pragma unroll
            for (int rr = 0; rr < 4; rr++) {
                float bv = s_b[(q * 4 + rr) * 16 + r];
                acc[rr][0] += bv * a0.x; acc[rr][1] += bv * a0.y;
                acc[rr][2] += bv * a0.z; acc[rr][3] += bv * a0.w;
                acc[rr][4] += bv * a1.x; acc[rr][5] += bv * a1.y;
                acc[rr][6] += bv * a1.z; acc[rr][7] += bv * a1.w;
            }
        }
        #pragma unroll
        for (int rr = 0; rr < 4; rr++) {
            const int o = ob + q * 4 + rr;
            uint4 v;
            v.x = h2u(__floats2half2_rn(acc[rr][0], acc[rr][1]));
            v.y = h2u(__floats2half2_rn(acc[rr][2], acc[rr][3]));
            v.z = h2u(__floats2half2_rn(acc[rr][4], acc[rr][5]));
            v.w = h2u(__floats2half2_rn(acc[rr][6], acc[rr][7]));
            size_t blk = ((size_t)((o >> 8) * 64 + (i0 >> 6))) << 15;
            uint32_t inner = swz128(((o & 255) << 7) | ((i0 & 63) << 1));
            *reinterpret_cast<uint4*>(reinterpret_cast<char*>(g_w16) + blk + inner) = v;
        }
    }
}

// ----------------------------------------------------------------------------
// Kernel 3: HMMA GEMM, CTA 128x128, 128 threads = 4 warps (2m x 2n, 64x64
// warp tiles — keeps R6's 4:1 MMA:LDSM ratio and ks+1 register prefetch).
// 3-stage cp.async pipeline, 96 KB smem -> 2 independent CTAs per SM: the
// sibling CTA's warps cover this CTA's barrier wait and post-barrier
// ldmatrix bubble.
// ----------------------------------------------------------------------------
__global__ void __launch_bounds__(128, 2) gemm_kernel(float* __restrict__ out) {
    extern __shared__ char smem[];
    const uint32_t sb = smem_u32(smem);
    const int tid = threadIdx.x;
    const int lane = tid & 31, wid = tid >> 5;
    const int wm = wid >> 1, wn = wid & 1;      // warp tile: 64x64
    const int bid = blockIdx.x;
    const int nt = bid & 31, mt = bid >> 5;     // n-minor: W stays L2-resident

    const char* ablock = reinterpret_cast<const char*>(g_x16) + (((size_t)mt * 64) << 14);
    // W is stored in 256-row n-blocks of 32KB per k-chunk; a 128-row half of a
    // block is the contiguous 16KB half (swizzle only permutes within rows).
    const char* bblock = reinterpret_cast<const char*>(g_w16) +
                         (((size_t)(nt >> 1) * 64) << 15) + ((size_t)(nt & 1) << 14);

    // stage fill: contiguous memcpy (layout is pre-swizzled); 16 cp16/thread
    auto load_stage = [&](int chunk, int slot) {
        uint32_t sA = sb + slot * STG;
        const char* as = ablock + ((size_t)chunk << 14);
        #pragma unroll
        for (int p = 0; p < 8; p++)
            cp16(sA + tid * 16 + p * 2048, as + tid * 16 + p * 2048);
        uint32_t sB = sA + A_STG;
        const char* bs = bblock + ((size_t)chunk << 15);
        #pragma unroll
        for (int p = 0; p < 8; p++)
            cp16(sB + tid * 16 + p * 2048, bs + tid * 16 + p * 2048);
    };

    load_stage(0, 0); cp_commit();
    load_stage(1, 1); cp_commit();

    // per-lane ldmatrix address components
    const uint32_t xorv   = (lane & 7) << 4;
    const uint32_t arow_l = ((lane >> 3) & 1) * 8 + (lane & 7);
    const uint32_t acol_l = (lane >> 4) * 16;            // byte col half
    const uint32_t nrow_l = ((lane >> 4) << 3) + (lane & 7);
    const uint32_t bcol_l = ((lane >> 3) & 1) * 16;      // byte col half

    uint32_t afr[2][4][4], bfr[2][4][4];

    auto load_frags = [&](int buf, uint32_t aS, uint32_t bS, int ks) {
        #pragma unroll
        for (int mf = 0; mf < 4; mf++) {
            uint32_t arow = wm * 64 + mf * 16 + arow_l;
            ldm_x4(afr[buf][mf], aS + arow * 128 + (((uint32_t)(ks * 32) + acol_l) ^ xorv));
        }
        #pragma unroll
        for (int np = 0; np < 4; np++) {
            uint32_t nrow = wn * 64 + np * 16 + nrow_l;
            ldm_x4(bfr[buf][np], bS + nrow * 128 + (((uint32_t)(ks * 32) + bcol_l) ^ xorv));
        }
    };

    float acc[4][8][4];
    #pragma unroll
    for (int i = 0; i < 4; i++)
        #pragma unroll
        for (int j = 0; j < 8; j++)
            #pragma unroll
            for (int c = 0; c < 4; c++) acc[i][j][c] = 0.f;

    int sc = 0, sp = 2;   // consumer / producer slots (mod 3 ring)
    for (int i = 0; i < NKITER; i++) {
        cp_wait<1>();          // stage i arrived (last committed = stage i+1)
        __syncthreads();       // ...and visible; protects slot sp overwrite
        if (i + 2 < NKITER) load_stage(i + 2, sp);
        cp_commit();           // unconditional: keeps group numbering exact

        const uint32_t aS = sb + sc * STG;
        const uint32_t bS = aS + A_STG;
        load_frags(0, aS, bS, 0);   // bubble covered by sibling CTA
        #pragma unroll
        for (int ks = 0; ks < 4; ks++) {
            const int cur = ks & 1, nxt = cur ^ 1;
            if (ks < 3) load_frags(nxt, aS, bS, ks + 1);
            #pragma unroll
            for (int np = 0; np < 4; np++) {
                #pragma unroll
                for (int mf = 0; mf < 4; mf++) {
                    mma16816(acc[mf][2 * np],     afr[cur][mf], bfr[cur][np][0], bfr[cur][np][1]);
                    mma16816(acc[mf][2 * np + 1], afr[cur][mf], bfr[cur][np][2], bfr[cur][np][3]);
                }
            }
        }
        sc = (sc + 1 == STAGES) ? 0 : sc + 1;
        sp = (sp + 1 == STAGES) ? 0 : sp + 1;
    }

    // epilogue: direct fp32 stores
    #pragma unroll
    for (int mf = 0; mf < 4; mf++) {
        size_t row0 = (size_t)mt * BM + wm * 64 + mf * 16 + (lane >> 2);
        float* r0 = out + row0 * NDIM + (size_t)nt * BN + wn * 64 + (lane & 3) * 2;
        float* r1 = r0 + 8 * NDIM;
        #pragma unroll
        for (int nf = 0; nf < 8; nf++) {
            *reinterpret_cast<float2*>(r0 + nf * 8) = make_float2(acc[mf][nf][0], acc[mf][nf][1]);
            *reinterpret_cast<float2*>(r1 + nf * 8) = make_float2(acc[mf][nf][2], acc[mf][nf][3]);
        }
    }
}

// ----------------------------------------------------------------------------
// Launch
// ----------------------------------------------------------------------------
extern "C" void kernel_launch(void* const* d_in, const int* in_sizes, int n_in,
                              void* d_out, int out_size) {
    const float* x      = (const float*)d_in[0];
    const int*   codes  = (const int*)d_in[1];
    const float* scales = (const float*)d_in[2];
    const float* la     = (const float*)d_in[3];
    const float* lb     = (const float*)d_in[4];
    float* out = (float*)d_out;
    (void)in_sizes; (void)n_in; (void)out_size;

    cudaFuncSetAttribute(gemm_kernel, cudaFuncAttributeMaxDynamicSharedMemorySize, GEMM_SMEM);

    convert_x_kernel<<<(MDIM * (size_t)KDIM) / 8 / 256, 256>>>(x);
    dequant_kernel<<<NDIM / 16, 256>>>(codes, scales, la, lb);
    gemm_kernel<<<(MDIM / BM) * (NDIM / BN), 128, GEMM_SMEM>>>(out);
}

// round 13
// speedup vs baseline: 1.1326x; 1.0841x over previous
#include <cuda_runtime.h>
#include <cuda_fp16.h>
#include <cstdint>
#include <cstddef>

// ----------------------------------------------------------------------------
// Problem constants
// ----------------------------------------------------------------------------
#define MDIM 8192   // B*S = 4*2048
#define NDIM 4096   // OUT_DIM
#define KDIM 4096   // IN_DIM

// GEMM tiling (R6 winner): CTA 128x256, 256 threads, 4-stage pipeline
#define BM 128
#define BN 256
#define BK 64                       // fp16 elems per K chunk = 128 B rows
#define NKITER (KDIM / BK)          // 64
#define STAGES 4
#define A_STG 16384                 // 128 rows * 128 B
#define B_STG 32768                 // 256 rows * 128 B
#define STG (A_STG + B_STG)         // 49152
#define GEMM_SMEM (STAGES * STG)    // 196608

// prep grid split: first DQ_BLOCKS do dequant, rest do x-convert
#define DQ_BLOCKS (NDIM / 16)       // 256
#define CV_BLOCKS 16384

// Pre-tiled, pre-swizzled staging buffers (prep writes; GEMM cp.asyncs)
__device__ __align__(1024) __half g_x16[(size_t)MDIM * KDIM];  // 64 MB
__device__ __align__(1024) __half g_w16[(size_t)NDIM * KDIM];  // 32 MB

__constant__ float c_nf4[16] = {
    -1.0f, -0.6961928009986877f, -0.5250730514526367f, -0.39491748809814453f,
    -0.28444138169288635f, -0.18477343022823334f, -0.09105003625154495f, 0.0f,
    0.07958029955625534f, 0.16093020141124725f, 0.24611230194568634f,
    0.33791524171829224f, 0.44070982933044434f, 0.5626170039176941f,
    0.7229568362236328f, 1.0f};

// ----------------------------------------------------------------------------
// Helpers
// ----------------------------------------------------------------------------
__device__ __forceinline__ uint32_t smem_u32(const void* p) {
    uint32_t a;
    asm("{ .reg .u64 t; cvta.to.shared.u64 t, %1; cvt.u32.u64 %0, t; }" : "=r"(a) : "l"(p));
    return a;
}
__device__ __forceinline__ uint32_t swz128(uint32_t o) { return o ^ ((o >> 3) & 0x70); }
__device__ __forceinline__ uint32_t h2u(__half2 h) { return *reinterpret_cast<uint32_t*>(&h); }

__device__ __forceinline__ void cp16(uint32_t dst, const void* src) {
    asm volatile("cp.async.cg.shared.global [%0], [%1], 16;" :: "r"(dst), "l"(src));
}
__device__ __forceinline__ void cp_commit() {
    asm volatile("cp.async.commit_group;" ::: "memory");
}
template <int N>
__device__ __forceinline__ void cp_wait() {
    asm volatile("cp.async.wait_group %0;" :: "n"(N) : "memory");
}
__device__ __forceinline__ void ldm_x4(uint32_t* r, uint32_t addr) {
    asm volatile("ldmatrix.sync.aligned.m8n8.x4.shared.b16 {%0,%1,%2,%3}, [%4];"
                 : "=r"(r[0]), "=r"(r[1]), "=r"(r[2]), "=r"(r[3]) : "r"(addr));
}
__device__ __forceinline__ void mma16816(float* c, const uint32_t* a, uint32_t b0, uint32_t b1) {
    asm volatile(
        "mma.sync.aligned.m16n8k16.row.col.f32.f16.f16.f32 "
        "{%0,%1,%2,%3}, {%4,%5,%6,%7}, {%8,%9}, {%0,%1,%2,%3};"
        : "+f"(c[0]), "+f"(c[1]), "+f"(c[2]), "+f"(c[3])
        : "r"(a[0]), "r"(a[1]), "r"(a[2]), "r"(a[3]), "r"(b0), "r"(b1));
}

// ----------------------------------------------------------------------------
// Kernel 1 (merged prep): blocks [0, DQ_BLOCKS) dequantize W_eff; blocks
// [DQ_BLOCKS, DQ_BLOCKS+CV_BLOCKS) convert x. Dequant first so its traffic
// overlaps the long convert tail.
//
// x layout:  block (mt,kc) 16 KB at ((mt*64+kc)<<14); elem (r,c) at
//            swz128(r*128 + c*2).
// W layout:  256-row n-blocks, 32 KB per (block, k-chunk).
// ----------------------------------------------------------------------------
__global__ void __launch_bounds__(256) prep_kernel(
    const float* __restrict__ x, const int* __restrict__ codes,
    const float* __restrict__ scales, const float* __restrict__ la,
    const float* __restrict__ lb) {
    __shared__ float a_sm[16 * 512];     // lora_a chunk [16][512]
    __shared__ float s_scale[16 * 64];
    __shared__ float s_b[16 * 16];
    __shared__ float s_nf4[16];
    const int tid = threadIdx.x;

    if (blockIdx.x >= DQ_BLOCKS) {
        // ---------------- x fp32 -> fp16 (blocked SW128) ----------------
        size_t t = (size_t)(blockIdx.x - DQ_BLOCKS) * 256 + tid;
        size_t base = t * 8;
        const float4* xp = reinterpret_cast<const float4*>(x + base);
        float4 f0 = __ldg(xp), f1 = __ldg(xp + 1);
        uint32_t m = (uint32_t)(base >> 12);
        uint32_t k = (uint32_t)(base & 4095);
        uint32_t mt = m >> 7, r = m & 127, kc = k >> 6, c = k & 63;
        uint32_t off = swz128((r << 7) | (c << 1));
        uint4 v;
        v.x = h2u(__floats2half2_rn(f0.x, f0.y));
        v.y = h2u(__floats2half2_rn(f0.z, f0.w));
        v.z = h2u(__floats2half2_rn(f1.x, f1.y));
        v.w = h2u(__floats2half2_rn(f1.z, f1.w));
        *reinterpret_cast<uint4*>(reinterpret_cast<char*>(g_x16) +
                                  (((size_t)(mt * 64 + kc)) << 14) + off) = v;
        return;
    }

    // ---------------- W_eff = nf4[codes]*scale + 2*(b@a) ----------------
    const int ob = blockIdx.x * 16;

    for (int i = tid; i < 1024; i += 256) s_scale[i] = scales[(size_t)ob * 64 + i];
    s_b[tid] = lb[(size_t)ob * 16 + tid] * 2.0f;  // fold alpha/rank = 2
    if (tid < 16) s_nf4[tid] = c_nf4[tid];

    const int q = tid >> 6;       // row quad 0..3
    const int oct = tid & 63;     // col octet within 512-col chunk
    const float4* lap = reinterpret_cast<const float4*>(la);
    float4* a4 = reinterpret_cast<float4*>(a_sm);

    for (int c8 = 0; c8 < 8; c8++) {
        __syncthreads();
        for (int i = tid; i < 2048; i += 256) {
            int r = i >> 7, j = i & 127;
            a4[i] = __ldg(lap + (size_t)r * 1024 + c8 * 128 + j);
        }
        __syncthreads();

        const int i0 = c8 * 512 + oct * 8;  // absolute column
        float acc[4][8];
        #pragma unroll
        for (int rr = 0; rr < 4; rr++) {
            const int o = ob + q * 4 + rr;
            const int4* cp = reinterpret_cast<const int4*>(codes + (size_t)o * 4096 + i0);
            int4 c0 = __ldg(cp), c1 = __ldg(cp + 1);
            float sc = s_scale[(q * 4 + rr) * 64 + (i0 >> 6)];
            acc[rr][0] = s_nf4[c0.x & 15] * sc;
            acc[rr][1] = s_nf4[c0.y & 15] * sc;
            acc[rr][2] = s_nf4[c0.z & 15] * sc;
            acc[rr][3] = s_nf4[c0.w & 15] * sc;
            acc[rr][4] = s_nf4[c1.x & 15] * sc;
            acc[rr][5] = s_nf4[c1.y & 15] * sc;
            acc[rr][6] = s_nf4[c1.z & 15] * sc;
            acc[rr][7] = s_nf4[c1.w & 15] * sc;
        }
        #pragma unroll
        for (int r = 0; r < 16; r++) {
            float4 a0 = a4[r * 128 + oct * 2];
            float4 a1 = a4[r * 128 + oct * 2 + 1];
            #pragma unroll
            for (int rr = 0; rr < 4; rr++) {
                float bv = s_b[(q * 4 + rr) * 16 + r];
                acc[rr][0] += bv * a0.x; acc[rr][1] += bv * a0.y;
                acc[rr][2] += bv * a0.z; acc[rr][3] += bv * a0.w;
                acc[rr][4] += bv * a1.x; acc[rr][5] += bv * a1.y;
                acc[rr][6] += bv * a1.z; acc[rr][7] += bv * a1.w;
            }
        }
        #pragma unroll
        for (int rr = 0; rr < 4; rr++) {
            const int o = ob + q * 4 + rr;
            uint4 v;
            v.x = h2u(__floats2half2_rn(acc[rr][0], acc[rr][1]));
            v.y = h2u(__floats2half2_rn(acc[rr][2], acc[rr][3]));
            v.z = h2u(__floats2half2_rn(acc[rr][4], acc[rr][5]));
            v.w = h2u(__floats2half2_rn(acc[rr][6], acc[rr][7]));
            size_t blk = ((size_t)((o >> 8) * 64 + (i0 >> 6))) << 15;
            uint32_t inner = swz128(((o & 255) << 7) | ((i0 & 63) << 1));
            *reinterpret_cast<uint4*>(reinterpret_cast<char*>(g_w16) + blk + inner) = v;
        }
    }
}

// ----------------------------------------------------------------------------
// Kernel 2: HMMA GEMM (R6 winner + LSU reorder). CTA 128x256, BK=64, 4-stage
// cp.async pipeline, 256 threads = 8 warps (2m x 4n, 64x64 warp tiles).
// Register fragment double-buffering across ks steps AND the stage boundary
// (wait<1> makes stages i and i+1 resident). The 12 cp.async of the next
// stage are issued AFTER ks=0's MMA block so the tensor pipe restarts first
// after the barrier.
// ----------------------------------------------------------------------------
__global__ void __launch_bounds__(256, 1) gemm_kernel(float* __restrict__ out) {
    extern __shared__ char smem[];
    const uint32_t sb = smem_u32(smem);
    const int tid = threadIdx.x;
    const int lane = tid & 31, wid = tid >> 5;
    const int wm = wid >> 2, wn = wid & 3;      // warp tile: 64x64
    const int bid = blockIdx.x;
    const int nt = bid & 15, mt = bid >> 4;     // n-minor: W stays L2-resident

    const char* ablock = reinterpret_cast<const char*>(g_x16) + (((size_t)mt * 64) << 14);
    const char* bblock = reinterpret_cast<const char*>(g_w16) + (((size_t)nt * 64) << 15);

    // stage fill: contiguous memcpy (layout is pre-swizzled)
    auto load_stage = [&](int chunk, int slot) {
        uint32_t sA = sb + slot * STG;
        const char* as = ablock + ((size_t)chunk << 14);
        #pragma unroll
        for (int p = 0; p < 4; p++)
            cp16(sA + tid * 16 + p * 4096, as + tid * 16 + p * 4096);
        uint32_t sB = sA + A_STG;
        const char* bs = bblock + ((size_t)chunk << 15);
        #pragma unroll
        for (int p = 0; p < 8; p++)
            cp16(sB + tid * 16 + p * 4096, bs + tid * 16 + p * 4096);
    };

    #pragma unroll
    for (int s = 0; s < STAGES - 1; s++) { load_stage(s, s); cp_commit(); }

    // per-lane ldmatrix address components
    const uint32_t xorv   = (lane & 7) << 4;
    const uint32_t arow_l = ((lane >> 3) & 1) * 8 + (lane & 7);
    const uint32_t acol_l = (lane >> 4) * 16;            // byte col half
    const uint32_t nrow_l = ((lane >> 4) << 3) + (lane & 7);
    const uint32_t bcol_l = ((lane >> 3) & 1) * 16;      // byte col half

    uint32_t afr[2][4][4], bfr[2][4][4];

    auto load_frags = [&](int buf, uint32_t aS, uint32_t bS, int ks) {
        #pragma unroll
        for (int mf = 0; mf < 4; mf++) {
            uint32_t arow = wm * 64 + mf * 16 + arow_l;
            ldm_x4(afr[buf][mf], aS + arow * 128 + (((uint32_t)(ks * 32) + acol_l) ^ xorv));
        }
        #pragma unroll
        for (int np = 0; np < 4; np++) {
            uint32_t nrow = wn * 64 + np * 16 + nrow_l;
            ldm_x4(bfr[buf][np], bS + nrow * 128 + (((uint32_t)(ks * 32) + bcol_l) ^ xorv));
        }
    };

    float acc[4][8][4];
    #pragma unroll
    for (int i = 0; i < 4; i++)
        #pragma unroll
        for (int j = 0; j < 8; j++)
            #pragma unroll
            for (int c = 0; c < 4; c++) acc[i][j][c] = 0.f;

    // peel: make stage 0 visible, preload its ks=0 fragments
    cp_wait<2>();
    __syncthreads();
    load_frags(0, sb, sb + A_STG, 0);

    for (int i = 0; i < NKITER; i++) {
        cp_wait<1>();          // stages i AND i+1 arrived
        __syncthreads();       // ...and visible to all warps

        const uint32_t aS = sb + (i & (STAGES - 1)) * STG;
        const uint32_t bS = aS + A_STG;
        int j = (i + 1 < NKITER) ? i + 1 : i;   // tail: dummy prefetch source
        const uint32_t aS2 = sb + (j & (STAGES - 1)) * STG;
        const uint32_t bS2 = aS2 + A_STG;

        #pragma unroll
        for (int ks = 0; ks < 4; ks++) {
            const int cur = ks & 1, nxt = cur ^ 1;
            if (ks < 3) load_frags(nxt, aS, bS, ks + 1);
            else        load_frags(nxt, aS2, bS2, 0);   // next stage's ks=0
            #pragma unroll
            for (int np = 0; np < 4; np++) {
                #pragma unroll
                for (int mf = 0; mf < 4; mf++) {
                    mma16816(acc[mf][2 * np],     afr[cur][mf], bfr[cur][np][0], bfr[cur][np][1]);
                    mma16816(acc[mf][2 * np + 1], afr[cur][mf], bfr[cur][np][2], bfr[cur][np][3]);
                }
            }
            // issue next-stage fill AFTER the first MMA block: tensor pipe
            // restarts before the 12 LDGSTS hit the LSU.
            if (ks == 0) {
                int nexti = i + STAGES - 1;
                if (nexti < NKITER) load_stage(nexti, nexti & (STAGES - 1));
                cp_commit();
            }
        }
    }

    // epilogue: direct fp32 stores
    #pragma unroll
    for (int mf = 0; mf < 4; mf++) {
        size_t row0 = (size_t)mt * BM + wm * 64 + mf * 16 + (lane >> 2);
        float* r0 = out + row0 * NDIM + (size_t)nt * BN + wn * 64 + (lane & 3) * 2;
        float* r1 = r0 + 8 * NDIM;
        #pragma unroll
        for (int nf = 0; nf < 8; nf++) {
            *reinterpret_cast<float2*>(r0 + nf * 8) = make_float2(acc[mf][nf][0], acc[mf][nf][1]);
            *reinterpret_cast<float2*>(r1 + nf * 8) = make_float2(acc[mf][nf][2], acc[mf][nf][3]);
        }
    }
}

// ----------------------------------------------------------------------------
// Launch
// ----------------------------------------------------------------------------
extern "C" void kernel_launch(void* const* d_in, const int* in_sizes, int n_in,
                              void* d_out, int out_size) {
    const float* x      = (const float*)d_in[0];
    const int*   codes  = (const int*)d_in[1];
    const float* scales = (const float*)d_in[2];
    const float* la     = (const float*)d_in[3];
    const float* lb     = (const float*)d_in[4];
    float* out = (float*)d_out;
    (void)in_sizes; (void)n_in; (void)out_size;

    cudaFuncSetAttribute(gemm_kernel, cudaFuncAttributeMaxDynamicSharedMemorySize, GEMM_SMEM);

    prep_kernel<<<DQ_BLOCKS + CV_BLOCKS, 256>>>(x, codes, scales, la, lb);
    gemm_kernel<<<(MDIM / BM) * (NDIM / BN), 256, GEMM_SMEM>>>(out);
}

// round 14
// speedup vs baseline: 1.1330x; 1.0003x over previous
#include <cuda_runtime.h>
#include <cuda_fp16.h>
#include <cstdint>
#include <cstddef>

// ----------------------------------------------------------------------------
// Problem constants
// ----------------------------------------------------------------------------
#define MDIM 8192   // B*S = 4*2048
#define NDIM 4096   // OUT_DIM
#define KDIM 4096   // IN_DIM

// GEMM tiling (R6 winner): CTA 128x256, 256 threads, 4-stage pipeline
#define BM 128
#define BN 256
#define BK 64                       // fp16 elems per K chunk = 128 B rows
#define NKITER (KDIM / BK)          // 64
#define STAGES 4
#define A_STG 16384                 // 128 rows * 128 B
#define B_STG 32768                 // 256 rows * 128 B
#define STG (A_STG + B_STG)         // 49152
#define GEMM_SMEM (STAGES * STG)    // 196608

// prep grid split: first DQ_BLOCKS do dequant, rest do x-convert
#define DQ_BLOCKS (NDIM / 16)       // 256
#define CV_BLOCKS 16384

// Pre-tiled, pre-swizzled staging buffers (prep writes; GEMM cp.asyncs)
__device__ __align__(1024) __half g_x16[(size_t)MDIM * KDIM];  // 64 MB
__device__ __align__(1024) __half g_w16[(size_t)NDIM * KDIM];  // 32 MB

__constant__ float c_nf4[16] = {
    -1.0f, -0.6961928009986877f, -0.5250730514526367f, -0.39491748809814453f,
    -0.28444138169288635f, -0.18477343022823334f, -0.09105003625154495f, 0.0f,
    0.07958029955625534f, 0.16093020141124725f, 0.24611230194568634f,
    0.33791524171829224f, 0.44070982933044434f, 0.5626170039176941f,
    0.7229568362236328f, 1.0f};

// ----------------------------------------------------------------------------
// Helpers
// ----------------------------------------------------------------------------
__device__ __forceinline__ uint32_t smem_u32(const void* p) {
    uint32_t a;
    asm("{ .reg .u64 t; cvta.to.shared.u64 t, %1; cvt.u32.u64 %0, t; }" : "=r"(a) : "l"(p));
    return a;
}
__device__ __forceinline__ uint32_t swz128(uint32_t o) { return o ^ ((o >> 3) & 0x70); }
__device__ __forceinline__ uint32_t h2u(__half2 h) { return *reinterpret_cast<uint32_t*>(&h); }

__device__ __forceinline__ void cp16(uint32_t dst, const void* src) {
    asm volatile("cp.async.cg.shared.global [%0], [%1], 16;" :: "r"(dst), "l"(src));
}
__device__ __forceinline__ void cp_commit() {
    asm volatile("cp.async.commit_group;" ::: "memory");
}
template <int N>
__device__ __forceinline__ void cp_wait() {
    asm volatile("cp.async.wait_group %0;" :: "n"(N) : "memory");
}
__device__ __forceinline__ void ldm_x4(uint32_t* r, uint32_t addr) {
    asm volatile("ldmatrix.sync.aligned.m8n8.x4.shared.b16 {%0,%1,%2,%3}, [%4];"
                 : "=r"(r[0]), "=r"(r[1]), "=r"(r[2]), "=r"(r[3]) : "r"(addr));
}
__device__ __forceinline__ void mma16816(float* c, const uint32_t* a, uint32_t b0, uint32_t b1) {
    asm volatile(
        "mma.sync.aligned.m16n8k16.row.col.f32.f16.f16.f32 "
        "{%0,%1,%2,%3}, {%4,%5,%6,%7}, {%8,%9}, {%0,%1,%2,%3};"
        : "+f"(c[0]), "+f"(c[1]), "+f"(c[2]), "+f"(c[3])
        : "r"(a[0]), "r"(a[1]), "r"(a[2]), "r"(a[3]), "r"(b0), "r"(b1));
}

// ----------------------------------------------------------------------------
// Kernel 1 (merged prep): blocks [0, DQ_BLOCKS) dequantize W_eff; blocks
// [DQ_BLOCKS, DQ_BLOCKS+CV_BLOCKS) convert x. Dequant first so its traffic
// overlaps the long convert tail.
//
// x layout:  block (mt,kc) 16 KB at ((mt*64+kc)<<14); elem (r,c) at
//            swz128(r*128 + c*2).
// W layout:  256-row n-blocks, 32 KB per (block, k-chunk).
// ----------------------------------------------------------------------------
__global__ void __launch_bounds__(256) prep_kernel(
    const float* __restrict__ x, const int* __restrict__ codes,
    const float* __restrict__ scales, const float* __restrict__ la,
    const float* __restrict__ lb) {
    __shared__ float a_sm[16 * 512];     // lora_a chunk [16][512]
    __shared__ float s_scale[16 * 64];
    __shared__ float s_b[16 * 16];
    __shared__ float s_nf4[16];
    const int tid = threadIdx.x;

    if (blockIdx.x >= DQ_BLOCKS) {
        // ---------------- x fp32 -> fp16 (blocked SW128) ----------------
        size_t t = (size_t)(blockIdx.x - DQ_BLOCKS) * 256 + tid;
        size_t base = t * 8;
        const float4* xp = reinterpret_cast<const float4*>(x + base);
        float4 f0 = __ldg(xp), f1 = __ldg(xp + 1);
        uint32_t m = (uint32_t)(base >> 12);
        uint32_t k = (uint32_t)(base & 4095);
        uint32_t mt = m >> 7, r = m & 127, kc = k >> 6, c = k & 63;
        uint32_t off = swz128((r << 7) | (c << 1));
        uint4 v;
        v.x = h2u(__floats2half2_rn(f0.x, f0.y));
        v.y = h2u(__floats2half2_rn(f0.z, f0.w));
        v.z = h2u(__floats2half2_rn(f1.x, f1.y));
        v.w = h2u(__floats2half2_rn(f1.z, f1.w));
        *reinterpret_cast<uint4*>(reinterpret_cast<char*>(g_x16) +
                                  (((size_t)(mt * 64 + kc)) << 14) + off) = v;
        return;
    }

    // ---------------- W_eff = nf4[codes]*scale + 2*(b@a) ----------------
    const int ob = blockIdx.x * 16;

    for (int i = tid; i < 1024; i += 256) s_scale[i] = scales[(size_t)ob * 64 + i];
    s_b[tid] = lb[(size_t)ob * 16 + tid] * 2.0f;  // fold alpha/rank = 2
    if (tid < 16) s_nf4[tid] = c_nf4[tid];

    const int q = tid >> 6;       // row quad 0..3
    const int oct = tid & 63;     // col octet within 512-col chunk
    const float4* lap = reinterpret_cast<const float4*>(la);
    float4* a4 = reinterpret_cast<float4*>(a_sm);

    for (int c8 = 0; c8 < 8; c8++) {
        __syncthreads();
        for (int i = tid; i < 2048; i += 256) {
            int r = i >> 7, j = i & 127;
            a4[i] = __ldg(lap + (size_t)r * 1024 + c8 * 128 + j);
        }
        __syncthreads();

        const int i0 = c8 * 512 + oct * 8;  // absolute column
        float acc[4][8];
        #pragma unroll
        for (int rr = 0; rr < 4; rr++) {
            const int o = ob + q * 4 + rr;
            const int4* cp = reinterpret_cast<const int4*>(codes + (size_t)o * 4096 + i0);
            int4 c0 = __ldg(cp), c1 = __ldg(cp + 1);
            float sc = s_scale[(q * 4 + rr) * 64 + (i0 >> 6)];
            acc[rr][0] = s_nf4[c0.x & 15] * sc;
            acc[rr][1] = s_nf4[c0.y & 15] * sc;
            acc[rr][2] = s_nf4[c0.z & 15] * sc;
            acc[rr][3] = s_nf4[c0.w & 15] * sc;
            acc[rr][4] = s_nf4[c1.x & 15] * sc;
            acc[rr][5] = s_nf4[c1.y & 15] * sc;
            acc[rr][6] = s_nf4[c1.z & 15] * sc;
            acc[rr][7] = s_nf4[c1.w & 15] * sc;
        }
        #pragma unroll
        for (int r = 0; r < 16; r++) {
            float4 a0 = a4[r * 128 + oct * 2];
            float4 a1 = a4[r * 128 + oct * 2 + 1];
            #pragma unroll
            for (int rr = 0; rr < 4; rr++) {
                float bv = s_b[(q * 4 + rr) * 16 + r];
                acc[rr][0] += bv * a0.x; acc[rr][1] += bv * a0.y;
                acc[rr][2] += bv * a0.z; acc[rr][3] += bv * a0.w;
                acc[rr][4] += bv * a1.x; acc[rr][5] += bv * a1.y;
                acc[rr][6] += bv * a1.z; acc[rr][7] += bv * a1.w;
            }
        }
        #pragma unroll
        for (int rr = 0; rr < 4; rr++) {
            const int o = ob + q * 4 + rr;
            uint4 v;
            v.x = h2u(__floats2half2_rn(acc[rr][0], acc[rr][1]));
            v.y = h2u(__floats2half2_rn(acc[rr][2], acc[rr][3]));
            v.z = h2u(__floats2half2_rn(acc[rr][4], acc[rr][5]));
            v.w = h2u(__floats2half2_rn(acc[rr][6], acc[rr][7]));
            size_t blk = ((size_t)((o >> 8) * 64 + (i0 >> 6))) << 15;
            uint32_t inner = swz128(((o & 255) << 7) | ((i0 & 63) << 1));
            *reinterpret_cast<uint4*>(reinterpret_cast<char*>(g_w16) + blk + inner) = v;
        }
    }
}

// ----------------------------------------------------------------------------
// Kernel 2: HMMA GEMM (R6 winner + LSU reorder). CTA 128x256, BK=64, 4-stage
// cp.async pipeline, 256 threads = 8 warps (2m x 4n, 64x64 warp tiles).
// Register fragment double-buffering across ks steps AND the stage boundary
// (wait<1> makes stages i and i+1 resident). The 12 cp.async of the next
// stage are issued AFTER ks=0's MMA block so the tensor pipe restarts first
// after the barrier.
// ----------------------------------------------------------------------------
__global__ void __launch_bounds__(256, 1) gemm_kernel(float* __restrict__ out) {
    extern __shared__ char smem[];
    const uint32_t sb = smem_u32(smem);
    const int tid = threadIdx.x;
    const int lane = tid & 31, wid = tid >> 5;
    const int wm = wid >> 2, wn = wid & 3;      // warp tile: 64x64
    const int bid = blockIdx.x;
    const int nt = bid & 15, mt = bid >> 4;     // n-minor: W stays L2-resident

    const char* ablock = reinterpret_cast<const char*>(g_x16) + (((size_t)mt * 64) << 14);
    const char* bblock = reinterpret_cast<const char*>(g_w16) + (((size_t)nt * 64) << 15);

    // stage fill: contiguous memcpy (layout is pre-swizzled)
    auto load_stage = [&](int chunk, int slot) {
        uint32_t sA = sb + slot * STG;
        const char* as = ablock + ((size_t)chunk << 14);
        #pragma unroll
        for (int p = 0; p < 4; p++)
            cp16(sA + tid * 16 + p * 4096, as + tid * 16 + p * 4096);
        uint32_t sB = sA + A_STG;
        const char* bs = bblock + ((size_t)chunk << 15);
        #pragma unroll
        for (int p = 0; p < 8; p++)
            cp16(sB + tid * 16 + p * 4096, bs + tid * 16 + p * 4096);
    };

    #pragma unroll
    for (int s = 0; s < STAGES - 1; s++) { load_stage(s, s); cp_commit(); }

    // per-lane ldmatrix address components
    const uint32_t xorv   = (lane & 7) << 4;
    const uint32_t arow_l = ((lane >> 3) & 1) * 8 + (lane & 7);
    const uint32_t acol_l = (lane >> 4) * 16;            // byte col half
    const uint32_t nrow_l = ((lane >> 4) << 3) + (lane & 7);
    const uint32_t bcol_l = ((lane >> 3) & 1) * 16;      // byte col half

    uint32_t afr[2][4][4], bfr[2][4][4];

    auto load_frags = [&](int buf, uint32_t aS, uint32_t bS, int ks) {
        #pragma unroll
        for (int mf = 0; mf < 4; mf++) {
            uint32_t arow = wm * 64 + mf * 16 + arow_l;
            ldm_x4(afr[buf][mf], aS + arow * 128 + (((uint32_t)(ks * 32) + acol_l) ^ xorv));
        }
        #pragma unroll
        for (int np = 0; np < 4; np++) {
            uint32_t nrow = wn * 64 + np * 16 + nrow_l;
            ldm_x4(bfr[buf][np], bS + nrow * 128 + (((uint32_t)(ks * 32) + bcol_l) ^ xorv));
        }
    };

    float acc[4][8][4];
    #pragma unroll
    for (int i = 0; i < 4; i++)
        #pragma unroll
        for (int j = 0; j < 8; j++)
            #pragma unroll
            for (int c = 0; c < 4; c++) acc[i][j][c] = 0.f;

    // peel: make stage 0 visible, preload its ks=0 fragments
    cp_wait<2>();
    __syncthreads();
    load_frags(0, sb, sb + A_STG, 0);

    for (int i = 0; i < NKITER; i++) {
        cp_wait<1>();          // stages i AND i+1 arrived
        __syncthreads();       // ...and visible to all warps

        const uint32_t aS = sb + (i & (STAGES - 1)) * STG;
        const uint32_t bS = aS + A_STG;
        int j = (i + 1 < NKITER) ? i + 1 : i;   // tail: dummy prefetch source
        const uint32_t aS2 = sb + (j & (STAGES - 1)) * STG;
        const uint32_t bS2 = aS2 + A_STG;

        #pragma unroll
        for (int ks = 0; ks < 4; ks++) {
            const int cur = ks & 1, nxt = cur ^ 1;
            if (ks < 3) load_frags(nxt, aS, bS, ks + 1);
            else        load_frags(nxt, aS2, bS2, 0);   // next stage's ks=0
            #pragma unroll
            for (int np = 0; np < 4; np++) {
                #pragma unroll
                for (int mf = 0; mf < 4; mf++) {
                    mma16816(acc[mf][2 * np],     afr[cur][mf], bfr[cur][np][0], bfr[cur][np][1]);
                    mma16816(acc[mf][2 * np + 1], afr[cur][mf], bfr[cur][np][2], bfr[cur][np][3]);
                }
            }
            // issue next-stage fill AFTER the first MMA block: tensor pipe
            // restarts before the 12 LDGSTS hit the LSU.
            if (ks == 0) {
                int nexti = i + STAGES - 1;
                if (nexti < NKITER) load_stage(nexti, nexti & (STAGES - 1));
                cp_commit();
            }
        }
    }

    // epilogue: direct fp32 stores
    #pragma unroll
    for (int mf = 0; mf < 4; mf++) {
        size_t row0 = (size_t)mt * BM + wm * 64 + mf * 16 + (lane >> 2);
        float* r0 = out + row0 * NDIM + (size_t)nt * BN + wn * 64 + (lane & 3) * 2;
        float* r1 = r0 + 8 * NDIM;
        #pragma unroll
        for (int nf = 0; nf < 8; nf++) {
            *reinterpret_cast<float2*>(r0 + nf * 8) = make_float2(acc[mf][nf][0], acc[mf][nf][1]);
            *reinterpret_cast<float2*>(r1 + nf * 8) = make_float2(acc[mf][nf][2], acc[mf][nf][3]);
        }
    }
}

// ----------------------------------------------------------------------------
// Launch
// ----------------------------------------------------------------------------
extern "C" void kernel_launch(void* const* d_in, const int* in_sizes, int n_in,
                              void* d_out, int out_size) {
    const float* x      = (const float*)d_in[0];
    const int*   codes  = (const int*)d_in[1];
    const float* scales = (const float*)d_in[2];
    const float* la     = (const float*)d_in[3];
    const float* lb     = (const float*)d_in[4];
    float* out = (float*)d_out;
    (void)in_sizes; (void)n_in; (void)out_size;

    cudaFuncSetAttribute(gemm_kernel, cudaFuncAttributeMaxDynamicSharedMemorySize, GEMM_SMEM);

    prep_kernel<<<DQ_BLOCKS + CV_BLOCKS, 256>>>(x, codes, scales, la, lb);
    gemm_kernel<<<(MDIM / BM) * (NDIM / BN), 256, GEMM_SMEM>>>(out);
}